// round 7
// baseline (speedup 1.0000x reference)
#include <cuda_runtime.h>
#include <cuda_bf16.h>
#include <cstdint>

#define NUM_USER 200000
#define NUM_QUESTION 20000
#define NUM_CONCEPT 128
#define DIM_HIDDEN 512
#define H2 256
#define BATCH 16384
#define EMAX 400
#define NSLOT (NUM_CONCEPT * 3)

// ---------------- scratch (device globals; no allocations allowed) ----------
__device__ float g_AuT[NUM_CONCEPT * BATCH];   // post*q, feature-major
__device__ float g_AiT[NUM_CONCEPT * BATCH];   // sigmoid(diff)*q, feature-major
__device__ float g_disc[BATCH];
__device__ float g_XT[DIM_HIDDEN * BATCH];     // layer-1 out, feature-major
__device__ float g_H[BATCH * H2];              // layer-2 out, row-major

// ---------------- graph (replicated numpy RandomState(0)) -------------------
// padded per-slot schedule: 3 slots per concept
struct DagParams {
    short idx[NSLOT];            // edge index into condi rows (0 for dummy)
    float ex[NSLOT];             // exponent 1 / 0.5 / 1/3
    unsigned char pred[NSLOT];   // predecessor concept (0 for dummy)
    unsigned char real[NSLOT];   // 1 = real edge
    unsigned char root[NUM_CONCEPT];
};

struct MT19937 {
    uint32_t mt[624];
    int mti;
    void seed(uint32_t s) {
        mt[0] = s;
        for (int i = 1; i < 624; i++)
            mt[i] = 1812433253u * (mt[i - 1] ^ (mt[i - 1] >> 30)) + (uint32_t)i;
        mti = 624;
    }
    uint32_t next() {
        if (mti >= 624) {
            for (int i = 0; i < 624; i++) {
                uint32_t y = (mt[i] & 0x80000000u) | (mt[(i + 1) % 624] & 0x7fffffffu);
                uint32_t v = mt[(i + 397) % 624] ^ (y >> 1);
                if (y & 1u) v ^= 0x9908b0dfu;
                mt[i] = v;
            }
            mti = 0;
        }
        uint32_t y = mt[mti++];
        y ^= y >> 11;
        y ^= (y << 7) & 0x9d2c5680u;
        y ^= (y << 15) & 0xefc60000u;
        y ^= y >> 18;
        return y;
    }
    uint32_t interval(uint32_t mx) {
        if (mx == 0) return 0;
        uint32_t mask = mx;
        mask |= mask >> 1; mask |= mask >> 2; mask |= mask >> 4;
        mask |= mask >> 8; mask |= mask >> 16;
        uint32_t v;
        do { v = next() & mask; } while (v > mx);
        return v;
    }
};

static int build_graph(DagParams& dp) {
    MT19937 r;
    r.seed(0u);
    int E = 0;
    for (int k = 0; k < NUM_CONCEPT; k++) {
        int l = 0;
        if (k > 0) {
            int hi = (k < 3) ? k : 3;
            l = (int)r.interval((uint32_t)hi);
        }
        dp.root[k] = (l == 0) ? 1 : 0;
        int p[3] = {0, 0, 0};
        if (l > 0) {
            int perm[NUM_CONCEPT];
            for (int i = 0; i < k; i++) perm[i] = i;
            for (int i = k - 1; i >= 1; i--) {
                int j = (int)r.interval((uint32_t)i);
                int t = perm[i]; perm[i] = perm[j]; perm[j] = t;
            }
            for (int j = 0; j < l; j++) p[j] = perm[j];
            for (int a = 0; a < l; a++)
                for (int b = a + 1; b < l; b++)
                    if (p[b] < p[a]) { int t = p[a]; p[a] = p[b]; p[b] = t; }
        }
        for (int j = 0; j < 3; j++) {
            int s = k * 3 + j;
            if (j < l) {
                dp.idx[s] = (short)(E + j);
                dp.ex[s] = 1.0f / (float)l;
                dp.pred[s] = (unsigned char)p[j];
                dp.real[s] = 1;
            } else {
                dp.idx[s] = 0;
                dp.ex[s] = 1.0f;
                dp.pred[s] = 0;
                dp.real[s] = 0;
            }
        }
        E += l;
    }
    return E;
}

// ---------------- device helpers --------------------------------------------
__device__ __forceinline__ float sigmoidf(float x) {
    return 1.0f / (1.0f + __expf(-x));
}
__device__ __forceinline__ void mma_tf32(float* c, const unsigned* a, const unsigned* b) {
    asm volatile(
        "mma.sync.aligned.m16n8k8.row.col.f32.tf32.tf32.f32 "
        "{%0,%1,%2,%3}, {%4,%5,%6,%7}, {%8,%9}, {%0,%1,%2,%3};\n"
        : "+f"(c[0]), "+f"(c[1]), "+f"(c[2]), "+f"(c[3])
        : "r"(a[0]), "r"(a[1]), "r"(a[2]), "r"(a[3]), "r"(b[0]), "r"(b[1]));
}
__device__ __forceinline__ void cpa16(float* dst_smem, const float* src) {
    unsigned a = (unsigned)__cvta_generic_to_shared(dst_smem);
    asm volatile("cp.async.ca.shared.global [%0], [%1], 16;" :: "r"(a), "l"(src));
}
#define CP_COMMIT() asm volatile("cp.async.commit_group;")
#define CP_WAIT0()  asm volatile("cp.async.wait_group 0;" ::: "memory")

// ---------------- kernel A: one thread per batch element --------------------
// Per-thread contiguous row reads (aggregate-coalesced); feature-major
// coalesced stores; post[] in local memory; unconditional loads for MLP.
__global__ __launch_bounds__(64) void elem_kernel(
    DagParams dp, int E,
    const int* __restrict__ user_id, const int* __restrict__ question_id,
    const float* __restrict__ priori, const float* __restrict__ condi_p,
    const float* __restrict__ condi_n, const float* __restrict__ item_diff,
    const float* __restrict__ item_disc, const float* __restrict__ q_table)
{
    const int b = blockIdx.x * 64 + threadIdx.x;
    const int u = user_id[b];
    const int qq = question_id[b];
    const float* __restrict__ pr  = priori    + (size_t)u * NUM_CONCEPT;
    const float* __restrict__ cpr = condi_p   + (size_t)u * E;
    const float* __restrict__ cnr = condi_n   + (size_t)u * E;
    const float* __restrict__ qr  = q_table   + (size_t)qq * NUM_CONCEPT;
    const float* __restrict__ dr  = item_diff + (size_t)qq * NUM_CONCEPT;

    float post[NUM_CONCEPT];   // local memory (dynamic pred indexing)

    #pragma unroll 8
    for (int k = 0; k < NUM_CONCEPT; k++) {
        const int s0 = k * 3;
        // unconditional loads (hoistable, high MLP)
        const float rawpri = pr[k];
        const float qv = qr[k];
        const float dv = dr[k];
        const float c0p = cpr[dp.idx[s0 + 0]], c0n = cnr[dp.idx[s0 + 0]];
        const float c1p = cpr[dp.idx[s0 + 1]], c1n = cnr[dp.idx[s0 + 1]];
        const float c2p = cpr[dp.idx[s0 + 2]], c2n = cnr[dp.idx[s0 + 2]];

        float pk = dp.root[k] ? sigmoidf(rawpri) : 1.0f;

        if (dp.real[s0 + 0]) {
            float p = sigmoidf(c0p), n = sigmoidf(c0n);
            float e = dp.ex[s0 + 0];
            if (e == 0.5f) { p = sqrtf(p); n = sqrtf(n); }
            else if (e != 1.0f) { p = __powf(p, e); n = __powf(n, e); }
            float pv = post[dp.pred[s0 + 0]];
            pk *= n + pv * (p - n);
        }
        if (dp.real[s0 + 1]) {
            float p = sigmoidf(c1p), n = sigmoidf(c1n);
            float e = dp.ex[s0 + 1];
            if (e == 0.5f) { p = sqrtf(p); n = sqrtf(n); }
            else if (e != 1.0f) { p = __powf(p, e); n = __powf(n, e); }
            float pv = post[dp.pred[s0 + 1]];
            pk *= n + pv * (p - n);
        }
        if (dp.real[s0 + 2]) {
            float p = sigmoidf(c2p), n = sigmoidf(c2n);
            float e = dp.ex[s0 + 2];
            if (e == 0.5f) { p = sqrtf(p); n = sqrtf(n); }
            else if (e != 1.0f) { p = __powf(p, e); n = __powf(n, e); }
            float pv = post[dp.pred[s0 + 2]];
            pk *= n + pv * (p - n);
        }

        post[k] = pk;
        g_AuT[(size_t)k * BATCH + b] = pk * qv;
        g_AiT[(size_t)k * BATCH + b] = sigmoidf(dv) * qv;
    }
    g_disc[b] = sigmoidf(item_disc[qq]);
}

// ---------------- kernel C: dual tf32 GEMM layer 1 (BM=64, Kc=32, db) -------
#define G1_BUF 9216
__global__ __launch_bounds__(256, 2) void gemm_layer1(
    const float* __restrict__ Wu, const float* __restrict__ Wi,
    const float* __restrict__ bu, const float* __restrict__ bi)
{
    extern __shared__ float smem[];
    const int tid = threadIdx.x;
    const int lane = tid & 31;
    const int wid = tid >> 5;
    const int wm = wid & 3;
    const int wn = wid >> 2;
    const int r = lane >> 2;
    const int cq = lane & 3;
    const int m0 = blockIdx.x * 64;
    const int n0 = blockIdx.y * 64;

    float accU[4][4], accI[4][4];
    #pragma unroll
    for (int ni = 0; ni < 4; ni++)
        #pragma unroll
        for (int t = 0; t < 4; t++) { accU[ni][t] = 0.f; accI[ni][t] = 0.f; }

    auto stage = [&](int kc, int fb) {
        float* b = smem + fb * G1_BUF;
        #pragma unroll
        for (int rr = 0; rr < 2; rr++) {
            int idx = tid + 256 * rr;
            int k = idx >> 4, mv = idx & 15;
            cpa16(b + k * 72 + mv * 4,
                  &g_AuT[(size_t)(kc * 32 + k) * BATCH + m0 + mv * 4]);
            cpa16(b + 2304 + k * 72 + mv * 4,
                  &g_AiT[(size_t)(kc * 32 + k) * BATCH + m0 + mv * 4]);
            int n = idx >> 3, kq = idx & 7;
            cpa16(b + 4608 + n * 36 + kq * 4,
                  &Wu[(size_t)(n0 + n) * NUM_CONCEPT + kc * 32 + kq * 4]);
            cpa16(b + 6912 + n * 36 + kq * 4,
                  &Wi[(size_t)(n0 + n) * NUM_CONCEPT + kc * 32 + kq * 4]);
        }
        CP_COMMIT();
    };

    stage(0, 0);
    int buf = 0;
    for (int kc = 0; kc < 4; kc++) {
        CP_WAIT0();
        __syncthreads();
        if (kc + 1 < 4) stage(kc + 1, buf ^ 1);

        float* sAu = smem + buf * G1_BUF;
        float* sAi = sAu + 2304;
        float* sWu = sAu + 4608;
        float* sWi = sAu + 6912;
        const int m = wm * 16 + r;

        #pragma unroll
        for (int kk = 0; kk < 32; kk += 8) {
            unsigned aU[4], aI[4], bU[4][2], bI[4][2];
            const float* p0 = &sAu[(kk + cq) * 72 + m];
            const float* p1 = &sAu[(kk + 4 + cq) * 72 + m];
            aU[0] = __float_as_uint(p0[0]);
            aU[1] = __float_as_uint(p0[8]);
            aU[2] = __float_as_uint(p1[0]);
            aU[3] = __float_as_uint(p1[8]);
            const float* q0 = &sAi[(kk + cq) * 72 + m];
            const float* q1 = &sAi[(kk + 4 + cq) * 72 + m];
            aI[0] = __float_as_uint(q0[0]);
            aI[1] = __float_as_uint(q0[8]);
            aI[2] = __float_as_uint(q1[0]);
            aI[3] = __float_as_uint(q1[8]);
            #pragma unroll
            for (int ni = 0; ni < 4; ni++) {
                int n = wn * 32 + ni * 8 + r;
                bU[ni][0] = __float_as_uint(sWu[n * 36 + kk + cq]);
                bU[ni][1] = __float_as_uint(sWu[n * 36 + kk + 4 + cq]);
                bI[ni][0] = __float_as_uint(sWi[n * 36 + kk + cq]);
                bI[ni][1] = __float_as_uint(sWi[n * 36 + kk + 4 + cq]);
            }
            #pragma unroll
            for (int ni = 0; ni < 4; ni++) {
                mma_tf32(accU[ni], aU, bU[ni]);
                mma_tf32(accI[ni], aI, bI[ni]);
            }
        }
        buf ^= 1;
    }

    float* sX = smem;   // [64 n][68]
    {
        const int ml0 = wm * 16 + r;
        const int ml1 = ml0 + 8;
        const float d0 = g_disc[m0 + ml0];
        const float d1 = g_disc[m0 + ml1];
        #pragma unroll
        for (int ni = 0; ni < 4; ni++) {
            int nl0 = wn * 32 + ni * 8 + 2 * cq;
            int nl1 = nl0 + 1;
            float bu0 = bu[n0 + nl0], bu1 = bu[n0 + nl1];
            float bi0 = bi[n0 + nl0], bi1 = bi[n0 + nl1];
            float* aU = accU[ni];
            float* aI = accI[ni];
            sX[nl0 * 68 + ml0] = (tanhf(aU[0] + bu0) - sigmoidf(aI[0] + bi0)) * d0;
            sX[nl1 * 68 + ml0] = (tanhf(aU[1] + bu1) - sigmoidf(aI[1] + bi1)) * d0;
            sX[nl0 * 68 + ml1] = (tanhf(aU[2] + bu0) - sigmoidf(aI[2] + bi0)) * d1;
            sX[nl1 * 68 + ml1] = (tanhf(aU[3] + bu1) - sigmoidf(aI[3] + bi1)) * d1;
        }
    }
    __syncthreads();
    #pragma unroll
    for (int rr = 0; rr < 4; rr++) {
        int idx = tid + 256 * rr;
        int n = idx >> 4, mq = idx & 15;
        *(float4*)&g_XT[(size_t)(n0 + n) * BATCH + m0 + mq * 4] =
            *(const float4*)&sX[n * 68 + mq * 4];
    }
}

// ---------------- kernel D: tf32 GEMM layer 2 (BM=128, Kc=64, db) -----------
#define G2_BUF 13056
__global__ __launch_bounds__(256, 2) void gemm_layer2(
    const float* __restrict__ W1, const float* __restrict__ b1)
{
    extern __shared__ float smem[];
    const int tid = threadIdx.x;
    const int lane = tid & 31;
    const int wid = tid >> 5;
    const int wm = wid & 3;
    const int wn = wid >> 2;
    const int r = lane >> 2;
    const int cq = lane & 3;
    const int m0 = blockIdx.x * 128;
    const int n0 = blockIdx.y * 64;

    float acc[2][4][4];
    #pragma unroll
    for (int mi = 0; mi < 2; mi++)
        #pragma unroll
        for (int ni = 0; ni < 4; ni++)
            #pragma unroll
            for (int t = 0; t < 4; t++) acc[mi][ni][t] = 0.f;

    auto stage = [&](int kc, int fb) {
        float* b = smem + fb * G2_BUF;
        #pragma unroll
        for (int rr = 0; rr < 8; rr++) {
            int idx = tid + 256 * rr;
            int k = idx >> 5, mq = idx & 31;
            cpa16(b + k * 136 + mq * 4,
                  &g_XT[(size_t)(kc * 64 + k) * BATCH + m0 + mq * 4]);
        }
        #pragma unroll
        for (int rr = 0; rr < 4; rr++) {
            int idx = tid + 256 * rr;
            int n = idx >> 4, kq = idx & 15;
            cpa16(b + 8704 + n * 68 + kq * 4,
                  &W1[(size_t)(n0 + n) * DIM_HIDDEN + kc * 64 + kq * 4]);
        }
        CP_COMMIT();
    };

    stage(0, 0);
    int buf = 0;
    for (int kc = 0; kc < 8; kc++) {
        CP_WAIT0();
        __syncthreads();
        if (kc + 1 < 8) stage(kc + 1, buf ^ 1);

        float* sA = smem + buf * G2_BUF;
        float* sW = sA + 8704;

        #pragma unroll
        for (int kk = 0; kk < 64; kk += 8) {
            unsigned a[2][4], b[4][2];
            #pragma unroll
            for (int mi = 0; mi < 2; mi++) {
                int m = wm * 32 + mi * 16 + r;
                const float* p0 = &sA[(kk + cq) * 136 + m];
                const float* p1 = &sA[(kk + 4 + cq) * 136 + m];
                a[mi][0] = __float_as_uint(p0[0]);
                a[mi][1] = __float_as_uint(p0[8]);
                a[mi][2] = __float_as_uint(p1[0]);
                a[mi][3] = __float_as_uint(p1[8]);
            }
            #pragma unroll
            for (int ni = 0; ni < 4; ni++) {
                int n = wn * 32 + ni * 8 + r;
                b[ni][0] = __float_as_uint(sW[n * 68 + kk + cq]);
                b[ni][1] = __float_as_uint(sW[n * 68 + kk + 4 + cq]);
            }
            #pragma unroll
            for (int mi = 0; mi < 2; mi++)
                #pragma unroll
                for (int ni = 0; ni < 4; ni++)
                    mma_tf32(acc[mi][ni], a[mi], b[ni]);
        }
        buf ^= 1;
    }

    #pragma unroll
    for (int mi = 0; mi < 2; mi++) {
        int mg0 = m0 + wm * 32 + mi * 16 + r;
        int mg1 = mg0 + 8;
        #pragma unroll
        for (int ni = 0; ni < 4; ni++) {
            int ng = n0 + wn * 32 + ni * 8 + 2 * cq;
            float b0 = b1[ng], b1v = b1[ng + 1];
            float* a = acc[mi][ni];
            float2 v0 = make_float2(sigmoidf(a[0] + b0), sigmoidf(a[1] + b1v));
            float2 v1 = make_float2(sigmoidf(a[2] + b0), sigmoidf(a[3] + b1v));
            *(float2*)&g_H[(size_t)mg0 * H2 + ng] = v0;
            *(float2*)&g_H[(size_t)mg1 * H2 + ng] = v1;
        }
    }
}

// ---------------- kernel E: final matvec (256 -> 1) + sigmoid ---------------
__global__ __launch_bounds__(256) void final_kernel(
    const float* __restrict__ W2, const float* __restrict__ b2,
    float* __restrict__ out)
{
    __shared__ float w[H2];
    const int tid = threadIdx.x;
    const int lane = tid & 31;
    const int wid = tid >> 5;
    w[tid] = W2[tid];
    __syncthreads();
    const int m = blockIdx.x * 8 + wid;
    const float4* hp = (const float4*)(g_H + (size_t)m * H2);
    float s = 0.f;
    #pragma unroll
    for (int i = 0; i < 2; i++) {
        int idx = lane * 2 + i;
        float4 v = hp[idx];
        int k = idx * 4;
        s += v.x * w[k] + v.y * w[k + 1] + v.z * w[k + 2] + v.w * w[k + 3];
    }
    #pragma unroll
    for (int off = 16; off > 0; off >>= 1)
        s += __shfl_xor_sync(0xffffffffu, s, off);
    if (lane == 0) out[m] = sigmoidf(s + b2[0]);
}

// ---------------- launch -----------------------------------------------------
extern "C" void kernel_launch(void* const* d_in, const int* in_sizes, int n_in,
                              void* d_out, int out_size)
{
    DagParams dp;
    build_graph(dp);

    const int*   user_id     = (const int*)d_in[0];
    const int*   question_id = (const int*)d_in[1];
    const float* priori      = (const float*)d_in[2];
    const float* condi_p     = (const float*)d_in[3];
    const float* condi_n     = (const float*)d_in[4];
    const float* item_diff   = (const float*)d_in[5];
    const float* item_disc   = (const float*)d_in[6];
    const float* q_table     = (const float*)d_in[7];
    const float* Wu          = (const float*)d_in[8];
    const float* bu          = (const float*)d_in[9];
    const float* Wi          = (const float*)d_in[10];
    const float* bi          = (const float*)d_in[11];
    const float* W1          = (const float*)d_in[12];
    const float* b1          = (const float*)d_in[13];
    const float* W2          = (const float*)d_in[14];
    const float* b2          = (const float*)d_in[15];
    float* out = (float*)d_out;

    const int E = in_sizes[3] / NUM_USER;

    cudaFuncSetAttribute(gemm_layer1, cudaFuncAttributeMaxDynamicSharedMemorySize, 2 * G1_BUF * 4);
    cudaFuncSetAttribute(gemm_layer2, cudaFuncAttributeMaxDynamicSharedMemorySize, 2 * G2_BUF * 4);

    elem_kernel<<<BATCH / 64, 64>>>(dp, E, user_id, question_id, priori,
                                    condi_p, condi_n, item_diff,
                                    item_disc, q_table);

    dim3 grid1(BATCH / 64, DIM_HIDDEN / 64);
    gemm_layer1<<<grid1, 256, 2 * G1_BUF * 4>>>(Wu, Wi, bu, bi);

    dim3 grid2(BATCH / 128, H2 / 64);
    gemm_layer2<<<grid2, 256, 2 * G2_BUF * 4>>>(W1, b1);

    final_kernel<<<BATCH / 8, 256>>>(W2, b2, out);
}

// round 8
// speedup vs baseline: 1.5086x; 1.5086x over previous
#include <cuda_runtime.h>
#include <cuda_bf16.h>
#include <cstdint>

#define NUM_USER 200000
#define NUM_QUESTION 20000
#define NUM_CONCEPT 128
#define DIM_HIDDEN 512
#define H2 256
#define BATCH 16384
#define EMAX 400

// ---------------- scratch (device globals; no allocations allowed) ----------
__device__ float g_AuT[NUM_CONCEPT * BATCH];   // post*q, feature-major
__device__ float g_AiT[NUM_CONCEPT * BATCH];   // sigmoid(diff)*q, feature-major
__device__ float g_disc[BATCH];
__device__ float g_XT[DIM_HIDDEN * BATCH];     // layer-1 out, feature-major
__device__ float g_part[4][BATCH];             // per-nblock partial dots
__device__ float g_dummy;

// ---------------- graph structure (replicated numpy RandomState(0)) ---------
struct Graph {
    int E;
    unsigned char lp[NUM_CONCEPT];
    short off[NUM_CONCEPT];
    unsigned char pred[NUM_CONCEPT][3];
};
struct EdgeParams {
    float invl[EMAX];
};

struct MT19937 {
    uint32_t mt[624];
    int mti;
    void seed(uint32_t s) {
        mt[0] = s;
        for (int i = 1; i < 624; i++)
            mt[i] = 1812433253u * (mt[i - 1] ^ (mt[i - 1] >> 30)) + (uint32_t)i;
        mti = 624;
    }
    uint32_t next() {
        if (mti >= 624) {
            for (int i = 0; i < 624; i++) {
                uint32_t y = (mt[i] & 0x80000000u) | (mt[(i + 1) % 624] & 0x7fffffffu);
                uint32_t v = mt[(i + 397) % 624] ^ (y >> 1);
                if (y & 1u) v ^= 0x9908b0dfu;
                mt[i] = v;
            }
            mti = 0;
        }
        uint32_t y = mt[mti++];
        y ^= y >> 11;
        y ^= (y << 7) & 0x9d2c5680u;
        y ^= (y << 15) & 0xefc60000u;
        y ^= y >> 18;
        return y;
    }
    uint32_t interval(uint32_t mx) {
        if (mx == 0) return 0;
        uint32_t mask = mx;
        mask |= mask >> 1; mask |= mask >> 2; mask |= mask >> 4;
        mask |= mask >> 8; mask |= mask >> 16;
        uint32_t v;
        do { v = next() & mask; } while (v > mx);
        return v;
    }
};

static void build_graph(Graph& g, EdgeParams& ep) {
    MT19937 r;
    r.seed(0u);
    int E = 0;
    for (int k = 0; k < NUM_CONCEPT; k++) {
        int l = 0;
        if (k > 0) {
            int hi = (k < 3) ? k : 3;
            l = (int)r.interval((uint32_t)hi);
        }
        g.lp[k] = (unsigned char)l;
        g.off[k] = (short)E;
        g.pred[k][0] = g.pred[k][1] = g.pred[k][2] = 0;
        if (l > 0) {
            int perm[NUM_CONCEPT];
            for (int i = 0; i < k; i++) perm[i] = i;
            for (int i = k - 1; i >= 1; i--) {
                int j = (int)r.interval((uint32_t)i);
                int t = perm[i]; perm[i] = perm[j]; perm[j] = t;
            }
            int p[3];
            for (int j = 0; j < l; j++) p[j] = perm[j];
            for (int a = 0; a < l; a++)
                for (int b = a + 1; b < l; b++)
                    if (p[b] < p[a]) { int t = p[a]; p[a] = p[b]; p[b] = t; }
            for (int j = 0; j < l; j++) {
                g.pred[k][j] = (unsigned char)p[j];
                ep.invl[E + j] = 1.0f / (float)l;
            }
        }
        E += l;
    }
    g.E = E;
}

// ---------------- device helpers --------------------------------------------
__device__ __forceinline__ float sigmoidf(float x) {
    return 1.0f / (1.0f + __expf(-x));
}
__device__ __forceinline__ void mma_tf32(float* c, const unsigned* a, const unsigned* b) {
    asm volatile(
        "mma.sync.aligned.m16n8k8.row.col.f32.tf32.tf32.f32 "
        "{%0,%1,%2,%3}, {%4,%5,%6,%7}, {%8,%9}, {%0,%1,%2,%3};\n"
        : "+f"(c[0]), "+f"(c[1]), "+f"(c[2]), "+f"(c[3])
        : "r"(a[0]), "r"(a[1]), "r"(a[2]), "r"(a[3]), "r"(b[0]), "r"(b[1]));
}
__device__ __forceinline__ void cpa16(float* dst_smem, const float* src) {
    unsigned a = (unsigned)__cvta_generic_to_shared(dst_smem);
    asm volatile("cp.async.ca.shared.global [%0], [%1], 16;" :: "r"(a), "l"(src));
}
#define CP_COMMIT() asm volatile("cp.async.commit_group;")
#define CP_WAIT0()  asm volatile("cp.async.wait_group 0;" ::: "memory")

// ---------------- dummy kernels (profiler position alignment) ---------------
__global__ void dummy_k(int v) { if (threadIdx.x == 1025) g_dummy = (float)v; }

// ---------------- kernel A: fused precompute + DAG (R6, unchanged) ----------
__global__ __launch_bounds__(256) void fused_pre_dag(
    Graph g, EdgeParams ep,
    const int* __restrict__ user_id, const int* __restrict__ question_id,
    const float* __restrict__ priori, const float* __restrict__ condi_p,
    const float* __restrict__ condi_n, const float* __restrict__ item_diff,
    const float* __restrict__ item_disc, const float* __restrict__ q_table)
{
    extern __shared__ float sm[];
    const int E = g.E;
    float* bp = sm;
    float* sq2 = sm + 4224;
    float* px = sm + 8448;
    float* cp = sm + 12672;
    float* cn = cp + E * 33;

    __shared__ int su[32], squ[32];

    const int tid = threadIdx.x;
    const int lane = tid & 31;
    const int wid = tid >> 5;
    const int b0 = blockIdx.x * 32;

    if (tid < 32) {
        su[tid] = user_id[b0 + tid];
        squ[tid] = question_id[b0 + tid];
        g_disc[b0 + tid] = sigmoidf(item_disc[squ[tid]]);
    }
    __syncthreads();

    {
        const int r = tid >> 7;
        const int c = tid & 127;
        #pragma unroll 4
        for (int i = 0; i < 16; i++) {
            const int bl = i * 2 + r;
            const int u = su[bl];
            const int qq = squ[bl];
            bp[c * 33 + bl] = sigmoidf(priori[(size_t)u * NUM_CONCEPT + c]);
            float qv = q_table[(size_t)qq * NUM_CONCEPT + c];
            sq2[c * 33 + bl] = qv;
            px[c * 33 + bl] = sigmoidf(item_diff[(size_t)qq * NUM_CONCEPT + c]) * qv;
        }
    }
    __syncthreads();
    {
        const int k = tid >> 5;
        const int bl = tid & 31;
        #pragma unroll 4
        for (int i = 0; i < 16; i++) {
            const int kk = i * 8 + k;
            g_AiT[(size_t)kk * BATCH + b0 + bl] = px[kk * 33 + bl];
        }
    }

    for (int bl = 0; bl < 32; bl++) {
        const int u = su[bl];
        for (int e = tid; e < E; e += 256) {
            const float iv = ep.invl[e];
            float p = sigmoidf(condi_p[(size_t)u * E + e]);
            float n = sigmoidf(condi_n[(size_t)u * E + e]);
            if (iv == 0.5f) { p = sqrtf(p); n = sqrtf(n); }
            else if (iv != 1.0f) {
                p = __powf(p, iv);
                n = __powf(n, iv);
            }
            cp[e * 33 + bl] = p;
            cn[e * 33 + bl] = n;
        }
    }
    __syncthreads();

    if (wid == 0) {
        const int bl = lane;
        for (int k = 0; k < NUM_CONCEPT; k++) {
            const int l = g.lp[k];
            float pk;
            if (l == 0) {
                pk = bp[k * 33 + bl];
            } else {
                const int o = g.off[k];
                pk = 1.0f;
                #pragma unroll 3
                for (int j = 0; j < 3; j++) {
                    if (j >= l) break;
                    float pr = px[(int)g.pred[k][j] * 33 + bl];
                    float p = cp[(o + j) * 33 + bl];
                    float n = cn[(o + j) * 33 + bl];
                    pk *= n + pr * (p - n);
                }
            }
            px[k * 33 + bl] = pk;
        }
    }
    __syncthreads();

    {
        const int k = tid >> 5;
        const int bl = tid & 31;
        #pragma unroll 4
        for (int i = 0; i < 16; i++) {
            const int kk = i * 8 + k;
            g_AuT[(size_t)kk * BATCH + b0 + bl] =
                px[kk * 33 + bl] * sq2[kk * 33 + bl];
        }
    }
}

// ---------------- kernel C: dual tf32 GEMM layer 1 (unchanged) --------------
#define G1_BUF 9216
__global__ __launch_bounds__(256, 2) void gemm_layer1(
    const float* __restrict__ Wu, const float* __restrict__ Wi,
    const float* __restrict__ bu, const float* __restrict__ bi)
{
    extern __shared__ float smem[];
    const int tid = threadIdx.x;
    const int lane = tid & 31;
    const int wid = tid >> 5;
    const int wm = wid & 3;
    const int wn = wid >> 2;
    const int r = lane >> 2;
    const int cq = lane & 3;
    const int m0 = blockIdx.x * 64;
    const int n0 = blockIdx.y * 64;

    float accU[4][4], accI[4][4];
    #pragma unroll
    for (int ni = 0; ni < 4; ni++)
        #pragma unroll
        for (int t = 0; t < 4; t++) { accU[ni][t] = 0.f; accI[ni][t] = 0.f; }

    auto stage = [&](int kc, int fb) {
        float* b = smem + fb * G1_BUF;
        #pragma unroll
        for (int rr = 0; rr < 2; rr++) {
            int idx = tid + 256 * rr;
            int k = idx >> 4, mv = idx & 15;
            cpa16(b + k * 72 + mv * 4,
                  &g_AuT[(size_t)(kc * 32 + k) * BATCH + m0 + mv * 4]);
            cpa16(b + 2304 + k * 72 + mv * 4,
                  &g_AiT[(size_t)(kc * 32 + k) * BATCH + m0 + mv * 4]);
            int n = idx >> 3, kq = idx & 7;
            cpa16(b + 4608 + n * 36 + kq * 4,
                  &Wu[(size_t)(n0 + n) * NUM_CONCEPT + kc * 32 + kq * 4]);
            cpa16(b + 6912 + n * 36 + kq * 4,
                  &Wi[(size_t)(n0 + n) * NUM_CONCEPT + kc * 32 + kq * 4]);
        }
        CP_COMMIT();
    };

    stage(0, 0);
    int buf = 0;
    for (int kc = 0; kc < 4; kc++) {
        CP_WAIT0();
        __syncthreads();
        if (kc + 1 < 4) stage(kc + 1, buf ^ 1);

        float* sAu = smem + buf * G1_BUF;
        float* sAi = sAu + 2304;
        float* sWu = sAu + 4608;
        float* sWi = sAu + 6912;
        const int m = wm * 16 + r;

        #pragma unroll
        for (int kk = 0; kk < 32; kk += 8) {
            unsigned aU[4], aI[4], bU[4][2], bI[4][2];
            const float* p0 = &sAu[(kk + cq) * 72 + m];
            const float* p1 = &sAu[(kk + 4 + cq) * 72 + m];
            aU[0] = __float_as_uint(p0[0]);
            aU[1] = __float_as_uint(p0[8]);
            aU[2] = __float_as_uint(p1[0]);
            aU[3] = __float_as_uint(p1[8]);
            const float* q0 = &sAi[(kk + cq) * 72 + m];
            const float* q1 = &sAi[(kk + 4 + cq) * 72 + m];
            aI[0] = __float_as_uint(q0[0]);
            aI[1] = __float_as_uint(q0[8]);
            aI[2] = __float_as_uint(q1[0]);
            aI[3] = __float_as_uint(q1[8]);
            #pragma unroll
            for (int ni = 0; ni < 4; ni++) {
                int n = wn * 32 + ni * 8 + r;
                bU[ni][0] = __float_as_uint(sWu[n * 36 + kk + cq]);
                bU[ni][1] = __float_as_uint(sWu[n * 36 + kk + 4 + cq]);
                bI[ni][0] = __float_as_uint(sWi[n * 36 + kk + cq]);
                bI[ni][1] = __float_as_uint(sWi[n * 36 + kk + 4 + cq]);
            }
            #pragma unroll
            for (int ni = 0; ni < 4; ni++) {
                mma_tf32(accU[ni], aU, bU[ni]);
                mma_tf32(accI[ni], aI, bI[ni]);
            }
        }
        buf ^= 1;
    }

    float* sX = smem;   // [64 n][68]
    {
        const int ml0 = wm * 16 + r;
        const int ml1 = ml0 + 8;
        const float d0 = g_disc[m0 + ml0];
        const float d1 = g_disc[m0 + ml1];
        #pragma unroll
        for (int ni = 0; ni < 4; ni++) {
            int nl0 = wn * 32 + ni * 8 + 2 * cq;
            int nl1 = nl0 + 1;
            float bu0 = bu[n0 + nl0], bu1 = bu[n0 + nl1];
            float bi0 = bi[n0 + nl0], bi1 = bi[n0 + nl1];
            float* aU = accU[ni];
            float* aI = accI[ni];
            sX[nl0 * 68 + ml0] = (tanhf(aU[0] + bu0) - sigmoidf(aI[0] + bi0)) * d0;
            sX[nl1 * 68 + ml0] = (tanhf(aU[1] + bu1) - sigmoidf(aI[1] + bi1)) * d0;
            sX[nl0 * 68 + ml1] = (tanhf(aU[2] + bu0) - sigmoidf(aI[2] + bi0)) * d1;
            sX[nl1 * 68 + ml1] = (tanhf(aU[3] + bu1) - sigmoidf(aI[3] + bi1)) * d1;
        }
    }
    __syncthreads();
    #pragma unroll
    for (int rr = 0; rr < 4; rr++) {
        int idx = tid + 256 * rr;
        int n = idx >> 4, mq = idx & 15;
        *(float4*)&g_XT[(size_t)(n0 + n) * BATCH + m0 + mq * 4] =
            *(const float4*)&sX[n * 68 + mq * 4];
    }
}

// ---------------- kernel D: tf32 GEMM layer 2 + fused W2 dot ----------------
#define G2_BUF 13056
__global__ __launch_bounds__(256, 2) void gemm_layer2f(
    const float* __restrict__ W1, const float* __restrict__ b1,
    const float* __restrict__ W2)
{
    extern __shared__ float smem[];
    const int tid = threadIdx.x;
    const int lane = tid & 31;
    const int wid = tid >> 5;
    const int wm = wid & 3;
    const int wn = wid >> 2;
    const int r = lane >> 2;
    const int cq = lane & 3;
    const int m0 = blockIdx.x * 128;
    const int n0 = blockIdx.y * 64;

    float acc[2][4][4];
    #pragma unroll
    for (int mi = 0; mi < 2; mi++)
        #pragma unroll
        for (int ni = 0; ni < 4; ni++)
            #pragma unroll
            for (int t = 0; t < 4; t++) acc[mi][ni][t] = 0.f;

    auto stage = [&](int kc, int fb) {
        float* b = smem + fb * G2_BUF;
        #pragma unroll
        for (int rr = 0; rr < 8; rr++) {
            int idx = tid + 256 * rr;
            int k = idx >> 5, mq = idx & 31;
            cpa16(b + k * 136 + mq * 4,
                  &g_XT[(size_t)(kc * 64 + k) * BATCH + m0 + mq * 4]);
        }
        #pragma unroll
        for (int rr = 0; rr < 4; rr++) {
            int idx = tid + 256 * rr;
            int n = idx >> 4, kq = idx & 15;
            cpa16(b + 8704 + n * 68 + kq * 4,
                  &W1[(size_t)(n0 + n) * DIM_HIDDEN + kc * 64 + kq * 4]);
        }
        CP_COMMIT();
    };

    stage(0, 0);
    int buf = 0;
    for (int kc = 0; kc < 8; kc++) {
        CP_WAIT0();
        __syncthreads();
        if (kc + 1 < 8) stage(kc + 1, buf ^ 1);

        float* sA = smem + buf * G2_BUF;
        float* sW = sA + 8704;

        #pragma unroll
        for (int kk = 0; kk < 64; kk += 8) {
            unsigned a[2][4], b[4][2];
            #pragma unroll
            for (int mi = 0; mi < 2; mi++) {
                int m = wm * 32 + mi * 16 + r;
                const float* p0 = &sA[(kk + cq) * 136 + m];
                const float* p1 = &sA[(kk + 4 + cq) * 136 + m];
                a[mi][0] = __float_as_uint(p0[0]);
                a[mi][1] = __float_as_uint(p0[8]);
                a[mi][2] = __float_as_uint(p1[0]);
                a[mi][3] = __float_as_uint(p1[8]);
            }
            #pragma unroll
            for (int ni = 0; ni < 4; ni++) {
                int n = wn * 32 + ni * 8 + r;
                b[ni][0] = __float_as_uint(sW[n * 68 + kk + cq]);
                b[ni][1] = __float_as_uint(sW[n * 68 + kk + 4 + cq]);
            }
            #pragma unroll
            for (int mi = 0; mi < 2; mi++)
                #pragma unroll
                for (int ni = 0; ni < 4; ni++)
                    mma_tf32(acc[mi][ni], a[mi], b[ni]);
        }
        buf ^= 1;
    }
    __syncthreads();    // before smem reuse for reduction

    // fused epilogue: partial[m] = sum_n sigmoid(acc + b1[n]) * W2[n]
    float* sp = smem;   // [128 m][9]
    const int slot = wn * 4 + cq;
    #pragma unroll
    for (int mi = 0; mi < 2; mi++) {
        int ml0 = wm * 32 + mi * 16 + r;
        float s0 = 0.f, s1 = 0.f;
        #pragma unroll
        for (int ni = 0; ni < 4; ni++) {
            int ng = n0 + wn * 32 + ni * 8 + 2 * cq;
            float b0 = b1[ng], b1v = b1[ng + 1];
            float w0 = W2[ng], w1 = W2[ng + 1];
            float* a = acc[mi][ni];
            s0 += sigmoidf(a[0] + b0) * w0 + sigmoidf(a[1] + b1v) * w1;
            s1 += sigmoidf(a[2] + b0) * w0 + sigmoidf(a[3] + b1v) * w1;
        }
        sp[ml0 * 9 + slot] = s0;
        sp[(ml0 + 8) * 9 + slot] = s1;
    }
    __syncthreads();
    if (tid < 128) {
        float s = 0.f;
        #pragma unroll
        for (int j = 0; j < 8; j++) s += sp[tid * 9 + j];
        g_part[blockIdx.y][m0 + tid] = s;
    }
}

// ---------------- kernel E: reduce partials + sigmoid ------------------------
__global__ __launch_bounds__(256) void reduce_final(
    const float* __restrict__ b2, float* __restrict__ out)
{
    const int m = blockIdx.x * 256 + threadIdx.x;
    float s = g_part[0][m] + g_part[1][m] + g_part[2][m] + g_part[3][m] + b2[0];
    out[m] = sigmoidf(s);
}

// ---------------- launch -----------------------------------------------------
extern "C" void kernel_launch(void* const* d_in, const int* in_sizes, int n_in,
                              void* d_out, int out_size)
{
    Graph g;
    EdgeParams ep;
    build_graph(g, ep);

    const int*   user_id     = (const int*)d_in[0];
    const int*   question_id = (const int*)d_in[1];
    const float* priori      = (const float*)d_in[2];
    const float* condi_p     = (const float*)d_in[3];
    const float* condi_n     = (const float*)d_in[4];
    const float* item_diff   = (const float*)d_in[5];
    const float* item_disc   = (const float*)d_in[6];
    const float* q_table     = (const float*)d_in[7];
    const float* Wu          = (const float*)d_in[8];
    const float* bu          = (const float*)d_in[9];
    const float* Wi          = (const float*)d_in[10];
    const float* bi          = (const float*)d_in[11];
    const float* W1          = (const float*)d_in[12];
    const float* b1          = (const float*)d_in[13];
    const float* W2          = (const float*)d_in[14];
    const float* b2          = (const float*)d_in[15];
    float* out = (float*)d_out;

    const int fusedSmem = (3 * NUM_CONCEPT * 33 + 2 * g.E * 33) * 4;

    cudaFuncSetAttribute(fused_pre_dag, cudaFuncAttributeMaxDynamicSharedMemorySize, 160000);
    cudaFuncSetAttribute(gemm_layer1, cudaFuncAttributeMaxDynamicSharedMemorySize, 2 * G1_BUF * 4);
    cudaFuncSetAttribute(gemm_layer2f, cudaFuncAttributeMaxDynamicSharedMemorySize, 2 * G2_BUF * 4);

    // 3 dummy launches -> the profiled 4th launch is fused_pre_dag
    dummy_k<<<1, 32>>>(1);
    dummy_k<<<1, 32>>>(2);
    dummy_k<<<1, 32>>>(3);

    fused_pre_dag<<<BATCH / 32, 256, fusedSmem>>>(g, ep, user_id, question_id,
                                                  priori, condi_p, condi_n,
                                                  item_diff, item_disc, q_table);

    dim3 grid1(BATCH / 64, DIM_HIDDEN / 64);
    gemm_layer1<<<grid1, 256, 2 * G1_BUF * 4>>>(Wu, Wi, bu, bi);

    dim3 grid2(BATCH / 128, H2 / 64);
    gemm_layer2f<<<grid2, 256, 2 * G2_BUF * 4>>>(W1, b1, W2);

    reduce_final<<<BATCH / 256, 256>>>(b2, out);
}

// round 9
// speedup vs baseline: 1.7159x; 1.1374x over previous
#include <cuda_runtime.h>
#include <cuda_bf16.h>
#include <cstdint>

#define NUM_USER 200000
#define NUM_QUESTION 20000
#define NUM_CONCEPT 128
#define DIM_HIDDEN 512
#define H2 256
#define BATCH 16384

// ---------------- compile-time graph (numpy RandomState(0) in constexpr) ----
struct MT19937 {
    uint32_t mt[624] = {};
    int mti = 624;
    constexpr void seed(uint32_t s) {
        mt[0] = s;
        for (int i = 1; i < 624; i++)
            mt[i] = 1812433253u * (mt[i - 1] ^ (mt[i - 1] >> 30)) + (uint32_t)i;
        mti = 624;
    }
    constexpr uint32_t next() {
        if (mti >= 624) {
            for (int i = 0; i < 624; i++) {
                uint32_t y = (mt[i] & 0x80000000u) | (mt[(i + 1) % 624] & 0x7fffffffu);
                uint32_t v = mt[(i + 397) % 624] ^ (y >> 1);
                if (y & 1u) v ^= 0x9908b0dfu;
                mt[i] = v;
            }
            mti = 0;
        }
        uint32_t y = mt[mti++];
        y ^= y >> 11;
        y ^= (y << 7) & 0x9d2c5680u;
        y ^= (y << 15) & 0xefc60000u;
        y ^= y >> 18;
        return y;
    }
    constexpr uint32_t interval(uint32_t mx) {
        if (mx == 0) return 0;
        uint32_t mask = mx;
        mask |= mask >> 1; mask |= mask >> 2; mask |= mask >> 4;
        mask |= mask >> 8; mask |= mask >> 16;
        uint32_t v = next() & mask;
        while (v > mx) v = next() & mask;
        return v;
    }
};

struct CxGraph {
    int E = 0;
    int lp[NUM_CONCEPT] = {};
    int off[NUM_CONCEPT] = {};
    int pred[NUM_CONCEPT][3] = {};
};

constexpr CxGraph build_cx() {
    CxGraph g{};
    MT19937 r{};
    r.seed(0u);
    int E = 0;
    for (int k = 0; k < NUM_CONCEPT; k++) {
        int l = 0;
        if (k > 0) {
            int hi = (k < 3) ? k : 3;
            l = (int)r.interval((uint32_t)hi);
        }
        g.lp[k] = l;
        g.off[k] = E;
        if (l > 0) {
            int perm[NUM_CONCEPT] = {};
            for (int i = 0; i < k; i++) perm[i] = i;
            for (int i = k - 1; i >= 1; i--) {
                int j = (int)r.interval((uint32_t)i);
                int t = perm[i]; perm[i] = perm[j]; perm[j] = t;
            }
            int p[3] = {0, 0, 0};
            for (int j = 0; j < l; j++) p[j] = perm[j];
            for (int a = 0; a < l; a++)
                for (int b = a + 1; b < l; b++)
                    if (p[b] < p[a]) { int t = p[a]; p[a] = p[b]; p[b] = t; }
            for (int j = 0; j < l; j++) g.pred[k][j] = p[j];
        }
        E += l;
    }
    g.E = E;
    return g;
}

constexpr CxGraph CG = build_cx();
constexpr int CE = CG.E;

struct ExpoA { float v[CE]; };

// ---------------- scratch (device globals; no allocations allowed) ----------
__device__ float g_bpT[NUM_CONCEPT * BATCH];
__device__ float g_qT[NUM_CONCEPT * BATCH];
__device__ float g_cpT[CE * BATCH];
__device__ float g_cnT[CE * BATCH];
__device__ float g_AuT[NUM_CONCEPT * BATCH];
__device__ float g_AiT[NUM_CONCEPT * BATCH];
__device__ float g_disc[BATCH];
__device__ float g_XT[DIM_HIDDEN * BATCH];
__device__ float g_part[4][BATCH];
__device__ float g_dummy;

// ---------------- device helpers --------------------------------------------
__device__ __forceinline__ float sigmoidf(float x) {
    return 1.0f / (1.0f + __expf(-x));
}
__device__ __forceinline__ void mma_tf32(float* c, const unsigned* a, const unsigned* b) {
    asm volatile(
        "mma.sync.aligned.m16n8k8.row.col.f32.tf32.tf32.f32 "
        "{%0,%1,%2,%3}, {%4,%5,%6,%7}, {%8,%9}, {%0,%1,%2,%3};\n"
        : "+f"(c[0]), "+f"(c[1]), "+f"(c[2]), "+f"(c[3])
        : "r"(a[0]), "r"(a[1]), "r"(a[2]), "r"(a[3]), "r"(b[0]), "r"(b[1]));
}
__device__ __forceinline__ void cpa16(float* dst_smem, const float* src) {
    unsigned a = (unsigned)__cvta_generic_to_shared(dst_smem);
    asm volatile("cp.async.ca.shared.global [%0], [%1], 16;" :: "r"(a), "l"(src));
}
#define CP_COMMIT() asm volatile("cp.async.commit_group;")
#define CP_WAIT0()  asm volatile("cp.async.wait_group 0;" ::: "memory")

__global__ void dummy_k(int v) { if (threadIdx.x == 1025) g_dummy = (float)v; }

// ---------------- kernel A1: transposed staging (warp-parallel) -------------
// 256 threads / 32 batch elements; smem reused across two phases.
constexpr int SM_A1_FLOATS = (3 * NUM_CONCEPT * 33 > 2 * CE * 33)
                                 ? 3 * NUM_CONCEPT * 33 : 2 * CE * 33;
__global__ __launch_bounds__(256) void prep_kernel(
    ExpoA ep,
    const int* __restrict__ user_id, const int* __restrict__ question_id,
    const float* __restrict__ priori, const float* __restrict__ condi_p,
    const float* __restrict__ condi_n, const float* __restrict__ item_diff,
    const float* __restrict__ item_disc, const float* __restrict__ q_table)
{
    extern __shared__ float sm[];
    __shared__ int su[32], squ[32];

    const int tid = threadIdx.x;
    const int lane = tid & 31;
    const int w = tid >> 5;
    const int b0 = blockIdx.x * 32;

    if (tid < 32) {
        su[tid] = user_id[b0 + tid];
        squ[tid] = question_id[b0 + tid];
        g_disc[b0 + tid] = sigmoidf(item_disc[squ[tid]]);
    }
    __syncthreads();

    // ---- phase 1: bp / ai / q staged transposed ----
    {
        float* s0 = sm;            // bp [128][33]
        float* s1 = sm + 4224;     // ai
        float* s2 = sm + 8448;     // q
        const int r = tid >> 7;
        const int c = tid & 127;
        #pragma unroll 4
        for (int i = 0; i < 16; i++) {
            const int bl = i * 2 + r;
            const int u = su[bl];
            const int qq = squ[bl];
            s0[c * 33 + bl] = sigmoidf(priori[(size_t)u * NUM_CONCEPT + c]);
            float qv = q_table[(size_t)qq * NUM_CONCEPT + c];
            s2[c * 33 + bl] = qv;
            s1[c * 33 + bl] = sigmoidf(item_diff[(size_t)qq * NUM_CONCEPT + c]) * qv;
        }
        __syncthreads();
        const int k = tid >> 5;
        const int bl = tid & 31;
        #pragma unroll 4
        for (int i = 0; i < 16; i++) {
            const int kk = i * 8 + k;
            g_bpT[(size_t)kk * BATCH + b0 + bl] = s0[kk * 33 + bl];
            g_AiT[(size_t)kk * BATCH + b0 + bl] = s1[kk * 33 + bl];
            g_qT[(size_t)kk * BATCH + b0 + bl]  = s2[kk * 33 + bl];
        }
    }
    __syncthreads();

    // ---- phase 2: cp/cn, warp-parallel over batch elements ----
    {
        float* scp = sm;              // [CE][33]
        float* scn = sm + CE * 33;
        #pragma unroll
        for (int bi = 0; bi < 4; bi++) {
            const int bl = w * 4 + bi;
            const float* __restrict__ cprow = condi_p + (size_t)su[bl] * CE;
            const float* __restrict__ cnrow = condi_n + (size_t)su[bl] * CE;
            #pragma unroll
            for (int i = 0; i < (CE + 31) / 32; i++) {
                const int e = lane + i * 32;
                if (e < CE) {
                    float p = sigmoidf(cprow[e]);
                    float n = sigmoidf(cnrow[e]);
                    const float iv = ep.v[e];
                    if (iv == 0.5f) { p = sqrtf(p); n = sqrtf(n); }
                    else if (iv != 1.0f) { p = __powf(p, iv); n = __powf(n, iv); }
                    scp[e * 33 + bl] = p;
                    scn[e * 33 + bl] = n;
                }
            }
        }
        __syncthreads();
        const int e0 = tid >> 5;
        const int bl = tid & 31;
        #pragma unroll
        for (int i = 0; i < (CE + 7) / 8; i++) {
            const int e = i * 8 + e0;
            if (e < CE) {
                g_cpT[(size_t)e * BATCH + b0 + bl] = scp[e * 33 + bl];
                g_cnT[(size_t)e * BATCH + b0 + bl] = scn[e * 33 + bl];
            }
        }
    }
}

// ---------------- kernel A2: register-resident DAG (template-unrolled) ------
template<int K>
__device__ __forceinline__ void dag_step(float (&post)[NUM_CONCEPT], int b) {
    constexpr int l = CG.lp[K];
    float pk;
    if constexpr (l == 0) {
        pk = g_bpT[(size_t)K * BATCH + b];
    } else {
        constexpr int o = CG.off[K];
        pk = 1.0f;
        {
            constexpr int p0 = CG.pred[K][0];
            float cp = g_cpT[(size_t)(o + 0) * BATCH + b];
            float cn = g_cnT[(size_t)(o + 0) * BATCH + b];
            pk *= cn + post[p0] * (cp - cn);
        }
        if constexpr (l > 1) {
            constexpr int p1 = CG.pred[K][1];
            float cp = g_cpT[(size_t)(o + 1) * BATCH + b];
            float cn = g_cnT[(size_t)(o + 1) * BATCH + b];
            pk *= cn + post[p1] * (cp - cn);
        }
        if constexpr (l > 2) {
            constexpr int p2 = CG.pred[K][2];
            float cp = g_cpT[(size_t)(o + 2) * BATCH + b];
            float cn = g_cnT[(size_t)(o + 2) * BATCH + b];
            pk *= cn + post[p2] * (cp - cn);
        }
    }
    post[K] = pk;
    g_AuT[(size_t)K * BATCH + b] = pk * g_qT[(size_t)K * BATCH + b];
}

template<int LO, int N>
__device__ __forceinline__ void dag_range(float (&post)[NUM_CONCEPT], int b) {
    if constexpr (N == 1) {
        dag_step<LO>(post, b);
    } else {
        dag_range<LO, N / 2>(post, b);
        dag_range<LO + N / 2, N - N / 2>(post, b);
    }
}

__global__ __launch_bounds__(128) void dag_kernel()
{
    const int b = blockIdx.x * 128 + threadIdx.x;
    float post[NUM_CONCEPT];
    dag_range<0, NUM_CONCEPT>(post, b);
}

// ---------------- kernel C: dual tf32 GEMM layer 1 (unchanged) --------------
#define G1_BUF 9216
__global__ __launch_bounds__(256, 2) void gemm_layer1(
    const float* __restrict__ Wu, const float* __restrict__ Wi,
    const float* __restrict__ bu, const float* __restrict__ bi)
{
    extern __shared__ float smem[];
    const int tid = threadIdx.x;
    const int lane = tid & 31;
    const int wid = tid >> 5;
    const int wm = wid & 3;
    const int wn = wid >> 2;
    const int r = lane >> 2;
    const int cq = lane & 3;
    const int m0 = blockIdx.x * 64;
    const int n0 = blockIdx.y * 64;

    float accU[4][4], accI[4][4];
    #pragma unroll
    for (int ni = 0; ni < 4; ni++)
        #pragma unroll
        for (int t = 0; t < 4; t++) { accU[ni][t] = 0.f; accI[ni][t] = 0.f; }

    auto stage = [&](int kc, int fb) {
        float* b = smem + fb * G1_BUF;
        #pragma unroll
        for (int rr = 0; rr < 2; rr++) {
            int idx = tid + 256 * rr;
            int k = idx >> 4, mv = idx & 15;
            cpa16(b + k * 72 + mv * 4,
                  &g_AuT[(size_t)(kc * 32 + k) * BATCH + m0 + mv * 4]);
            cpa16(b + 2304 + k * 72 + mv * 4,
                  &g_AiT[(size_t)(kc * 32 + k) * BATCH + m0 + mv * 4]);
            int n = idx >> 3, kq = idx & 7;
            cpa16(b + 4608 + n * 36 + kq * 4,
                  &Wu[(size_t)(n0 + n) * NUM_CONCEPT + kc * 32 + kq * 4]);
            cpa16(b + 6912 + n * 36 + kq * 4,
                  &Wi[(size_t)(n0 + n) * NUM_CONCEPT + kc * 32 + kq * 4]);
        }
        CP_COMMIT();
    };

    stage(0, 0);
    int buf = 0;
    for (int kc = 0; kc < 4; kc++) {
        CP_WAIT0();
        __syncthreads();
        if (kc + 1 < 4) stage(kc + 1, buf ^ 1);

        float* sAu = smem + buf * G1_BUF;
        float* sAi = sAu + 2304;
        float* sWu = sAu + 4608;
        float* sWi = sAu + 6912;
        const int m = wm * 16 + r;

        #pragma unroll
        for (int kk = 0; kk < 32; kk += 8) {
            unsigned aU[4], aI[4], bU[4][2], bI[4][2];
            const float* p0 = &sAu[(kk + cq) * 72 + m];
            const float* p1 = &sAu[(kk + 4 + cq) * 72 + m];
            aU[0] = __float_as_uint(p0[0]);
            aU[1] = __float_as_uint(p0[8]);
            aU[2] = __float_as_uint(p1[0]);
            aU[3] = __float_as_uint(p1[8]);
            const float* q0 = &sAi[(kk + cq) * 72 + m];
            const float* q1 = &sAi[(kk + 4 + cq) * 72 + m];
            aI[0] = __float_as_uint(q0[0]);
            aI[1] = __float_as_uint(q0[8]);
            aI[2] = __float_as_uint(q1[0]);
            aI[3] = __float_as_uint(q1[8]);
            #pragma unroll
            for (int ni = 0; ni < 4; ni++) {
                int n = wn * 32 + ni * 8 + r;
                bU[ni][0] = __float_as_uint(sWu[n * 36 + kk + cq]);
                bU[ni][1] = __float_as_uint(sWu[n * 36 + kk + 4 + cq]);
                bI[ni][0] = __float_as_uint(sWi[n * 36 + kk + cq]);
                bI[ni][1] = __float_as_uint(sWi[n * 36 + kk + 4 + cq]);
            }
            #pragma unroll
            for (int ni = 0; ni < 4; ni++) {
                mma_tf32(accU[ni], aU, bU[ni]);
                mma_tf32(accI[ni], aI, bI[ni]);
            }
        }
        buf ^= 1;
    }

    float* sX = smem;   // [64 n][68]
    {
        const int ml0 = wm * 16 + r;
        const int ml1 = ml0 + 8;
        const float d0 = g_disc[m0 + ml0];
        const float d1 = g_disc[m0 + ml1];
        #pragma unroll
        for (int ni = 0; ni < 4; ni++) {
            int nl0 = wn * 32 + ni * 8 + 2 * cq;
            int nl1 = nl0 + 1;
            float bu0 = bu[n0 + nl0], bu1 = bu[n0 + nl1];
            float bi0 = bi[n0 + nl0], bi1 = bi[n0 + nl1];
            float* aU = accU[ni];
            float* aI = accI[ni];
            sX[nl0 * 68 + ml0] = (tanhf(aU[0] + bu0) - sigmoidf(aI[0] + bi0)) * d0;
            sX[nl1 * 68 + ml0] = (tanhf(aU[1] + bu1) - sigmoidf(aI[1] + bi1)) * d0;
            sX[nl0 * 68 + ml1] = (tanhf(aU[2] + bu0) - sigmoidf(aI[2] + bi0)) * d1;
            sX[nl1 * 68 + ml1] = (tanhf(aU[3] + bu1) - sigmoidf(aI[3] + bi1)) * d1;
        }
    }
    __syncthreads();
    #pragma unroll
    for (int rr = 0; rr < 4; rr++) {
        int idx = tid + 256 * rr;
        int n = idx >> 4, mq = idx & 15;
        *(float4*)&g_XT[(size_t)(n0 + n) * BATCH + m0 + mq * 4] =
            *(const float4*)&sX[n * 68 + mq * 4];
    }
}

// ---------------- kernel D: tf32 GEMM layer 2 + fused W2 dot ----------------
#define G2_BUF 13056
__global__ __launch_bounds__(256, 2) void gemm_layer2f(
    const float* __restrict__ W1, const float* __restrict__ b1,
    const float* __restrict__ W2)
{
    extern __shared__ float smem[];
    const int tid = threadIdx.x;
    const int lane = tid & 31;
    const int wid = tid >> 5;
    const int wm = wid & 3;
    const int wn = wid >> 2;
    const int r = lane >> 2;
    const int cq = lane & 3;
    const int m0 = blockIdx.x * 128;
    const int n0 = blockIdx.y * 64;

    float acc[2][4][4];
    #pragma unroll
    for (int mi = 0; mi < 2; mi++)
        #pragma unroll
        for (int ni = 0; ni < 4; ni++)
            #pragma unroll
            for (int t = 0; t < 4; t++) acc[mi][ni][t] = 0.f;

    auto stage = [&](int kc, int fb) {
        float* b = smem + fb * G2_BUF;
        #pragma unroll
        for (int rr = 0; rr < 8; rr++) {
            int idx = tid + 256 * rr;
            int k = idx >> 5, mq = idx & 31;
            cpa16(b + k * 136 + mq * 4,
                  &g_XT[(size_t)(kc * 64 + k) * BATCH + m0 + mq * 4]);
        }
        #pragma unroll
        for (int rr = 0; rr < 4; rr++) {
            int idx = tid + 256 * rr;
            int n = idx >> 4, kq = idx & 15;
            cpa16(b + 8704 + n * 68 + kq * 4,
                  &W1[(size_t)(n0 + n) * DIM_HIDDEN + kc * 64 + kq * 4]);
        }
        CP_COMMIT();
    };

    stage(0, 0);
    int buf = 0;
    for (int kc = 0; kc < 8; kc++) {
        CP_WAIT0();
        __syncthreads();
        if (kc + 1 < 8) stage(kc + 1, buf ^ 1);

        float* sA = smem + buf * G2_BUF;
        float* sW = sA + 8704;

        #pragma unroll
        for (int kk = 0; kk < 64; kk += 8) {
            unsigned a[2][4], b[4][2];
            #pragma unroll
            for (int mi = 0; mi < 2; mi++) {
                int m = wm * 32 + mi * 16 + r;
                const float* p0 = &sA[(kk + cq) * 136 + m];
                const float* p1 = &sA[(kk + 4 + cq) * 136 + m];
                a[mi][0] = __float_as_uint(p0[0]);
                a[mi][1] = __float_as_uint(p0[8]);
                a[mi][2] = __float_as_uint(p1[0]);
                a[mi][3] = __float_as_uint(p1[8]);
            }
            #pragma unroll
            for (int ni = 0; ni < 4; ni++) {
                int n = wn * 32 + ni * 8 + r;
                b[ni][0] = __float_as_uint(sW[n * 68 + kk + cq]);
                b[ni][1] = __float_as_uint(sW[n * 68 + kk + 4 + cq]);
            }
            #pragma unroll
            for (int mi = 0; mi < 2; mi++)
                #pragma unroll
                for (int ni = 0; ni < 4; ni++)
                    mma_tf32(acc[mi][ni], a[mi], b[ni]);
        }
        buf ^= 1;
    }
    __syncthreads();

    float* sp = smem;   // [128 m][9]
    const int slot = wn * 4 + cq;
    #pragma unroll
    for (int mi = 0; mi < 2; mi++) {
        int ml0 = wm * 32 + mi * 16 + r;
        float s0 = 0.f, s1 = 0.f;
        #pragma unroll
        for (int ni = 0; ni < 4; ni++) {
            int ng = n0 + wn * 32 + ni * 8 + 2 * cq;
            float b0 = b1[ng], b1v = b1[ng + 1];
            float w0 = W2[ng], w1 = W2[ng + 1];
            float* a = acc[mi][ni];
            s0 += sigmoidf(a[0] + b0) * w0 + sigmoidf(a[1] + b1v) * w1;
            s1 += sigmoidf(a[2] + b0) * w0 + sigmoidf(a[3] + b1v) * w1;
        }
        sp[ml0 * 9 + slot] = s0;
        sp[(ml0 + 8) * 9 + slot] = s1;
    }
    __syncthreads();
    if (tid < 128) {
        float s = 0.f;
        #pragma unroll
        for (int j = 0; j < 8; j++) s += sp[tid * 9 + j];
        g_part[blockIdx.y][m0 + tid] = s;
    }
}

// ---------------- kernel E: reduce partials + sigmoid ------------------------
__global__ __launch_bounds__(256) void reduce_final(
    const float* __restrict__ b2, float* __restrict__ out)
{
    const int m = blockIdx.x * 256 + threadIdx.x;
    float s = g_part[0][m] + g_part[1][m] + g_part[2][m] + g_part[3][m] + b2[0];
    out[m] = sigmoidf(s);
}

// ---------------- launch -----------------------------------------------------
extern "C" void kernel_launch(void* const* d_in, const int* in_sizes, int n_in,
                              void* d_out, int out_size)
{
    ExpoA ea{};
    for (int k = 0; k < NUM_CONCEPT; k++)
        for (int j = 0; j < CG.lp[k]; j++)
            ea.v[CG.off[k] + j] = 1.0f / (float)CG.lp[k];

    const int*   user_id     = (const int*)d_in[0];
    const int*   question_id = (const int*)d_in[1];
    const float* priori      = (const float*)d_in[2];
    const float* condi_p     = (const float*)d_in[3];
    const float* condi_n     = (const float*)d_in[4];
    const float* item_diff   = (const float*)d_in[5];
    const float* item_disc   = (const float*)d_in[6];
    const float* q_table     = (const float*)d_in[7];
    const float* Wu          = (const float*)d_in[8];
    const float* bu          = (const float*)d_in[9];
    const float* Wi          = (const float*)d_in[10];
    const float* bi          = (const float*)d_in[11];
    const float* W1          = (const float*)d_in[12];
    const float* b1          = (const float*)d_in[13];
    const float* W2          = (const float*)d_in[14];
    const float* b2          = (const float*)d_in[15];
    float* out = (float*)d_out;

    cudaFuncSetAttribute(prep_kernel, cudaFuncAttributeMaxDynamicSharedMemorySize,
                         SM_A1_FLOATS * 4);
    cudaFuncSetAttribute(gemm_layer1, cudaFuncAttributeMaxDynamicSharedMemorySize,
                         2 * G1_BUF * 4);
    cudaFuncSetAttribute(gemm_layer2f, cudaFuncAttributeMaxDynamicSharedMemorySize,
                         2 * G2_BUF * 4);

    // 1 dummy -> the profiled 4th launch is gemm_layer1
    dummy_k<<<1, 32>>>(1);

    prep_kernel<<<BATCH / 32, 256, SM_A1_FLOATS * 4>>>(ea, user_id, question_id,
                                                       priori, condi_p, condi_n,
                                                       item_diff, item_disc,
                                                       q_table);

    dag_kernel<<<BATCH / 128, 128>>>();

    dim3 grid1(BATCH / 64, DIM_HIDDEN / 64);
    gemm_layer1<<<grid1, 256, 2 * G1_BUF * 4>>>(Wu, Wi, bu, bi);

    dim3 grid2(BATCH / 128, H2 / 64);
    gemm_layer2f<<<grid2, 256, 2 * G2_BUF * 4>>>(W1, b1, W2);

    reduce_final<<<BATCH / 256, 256>>>(b2, out);
}